// round 15
// baseline (speedup 1.0000x reference)
#include <cuda_runtime.h>
#include <cstdint>

typedef unsigned long long u64;

#define NB 16
#define NF 20
#define NT 128
#define ND 300
#define NH 256
#define NG 1024   // 4*H
#define SEQS 320  // NB*NF
#define NM 40960  // SEQS*NT
#define LNS 10    // sequences per lstm cluster (32 groups)

// Scratch: xz 335 MB, xT 49 MB, U repack 2 MB, mask 40 KB.
__device__ float g_xz[2ull * NM * NG];
__device__ float g_xT[(size_t)ND * NM];        // [k][m] transposed input
// U layout (R7): u64 idx = (((dc*128 + k2)*8 + q)*32 + cg5)*2 + kk
__device__ u64 g_U7[4 * 128 * 8 * 32 * 2];
__device__ unsigned char g_mask[SEQS * NT];

__device__ __forceinline__ u64 pack2(float a, float b){
    u64 r; asm("mov.b64 %0, {%1, %2};" : "=l"(r) : "f"(a), "f"(b)); return r;
}
__device__ __forceinline__ void unpack2(u64 v, float& a, float& b){
    asm("mov.b64 {%0, %1}, %2;" : "=f"(a), "=f"(b) : "l"(v));
}
__device__ __forceinline__ u64 ffma2(u64 a, u64 b, u64 c){
    u64 d; asm("fma.rn.f32x2 %0, %1, %2, %3;" : "=l"(d) : "l"(a), "l"(b), "l"(c)); return d;
}
__device__ __forceinline__ u64 addf32x2(u64 a, u64 b){
    u64 d; asm("add.rn.f32x2 %0, %1, %2;" : "=l"(d) : "l"(a), "l"(b)); return d;
}
__device__ __forceinline__ uint32_t smem_u32(const void* p){
    uint32_t a; asm("{ .reg .u64 t; cvta.to.shared.u64 t, %1; cvt.u32.u64 %0, t; }" : "=r"(a) : "l"(p));
    return a;
}
__device__ __forceinline__ uint32_t mapa_u32(uint32_t addr, uint32_t rank){
    uint32_t r; asm("mapa.shared::cluster.u32 %0, %1, %2;" : "=r"(r) : "r"(addr), "r"(rank));
    return r;
}
__device__ __forceinline__ void st_cluster_u64(uint32_t addr, u64 v){
    asm volatile("st.shared::cluster.u64 [%0], %1;" :: "r"(addr), "l"(v) : "memory");
}
__device__ __forceinline__ void cluster_sync(){
    asm volatile("barrier.cluster.arrive.aligned;\n\tbarrier.cluster.wait.aligned;" ::: "memory");
}
__device__ __forceinline__ void cp_async16(uint32_t sdst, const void* gsrc){
    asm volatile("cp.async.ca.shared.global [%0], [%1], 16;" :: "r"(sdst), "l"(gsrc) : "memory");
}
__device__ __forceinline__ void cp_async_commit(){
    asm volatile("cp.async.commit_group;" ::: "memory");
}
__device__ __forceinline__ void cp_async_wait0(){
    asm volatile("cp.async.wait_group 0;" ::: "memory");
}
__device__ __forceinline__ void cp_async_wait1(){
    asm volatile("cp.async.wait_group 1;" ::: "memory");
}

// ---------------------------------------------------------------------------
// Transpose x -> g_xT[k][m].
// ---------------------------------------------------------------------------
__global__ void repack_x_kernel(const float* __restrict__ x)
{
    size_t idx = (size_t)blockIdx.x * 256 + threadIdx.x;
    int k = (int)(idx / NM);
    int m = (int)(idx % NM);
    g_xT[idx] = x[(size_t)m * ND + k];
}

// ---------------------------------------------------------------------------
// Repack U into the R7 chunked layout.
// ---------------------------------------------------------------------------
__global__ void repack_u_kernel(const float* __restrict__ Uf, const float* __restrict__ Ub)
{
    int idx = blockIdx.x * 256 + threadIdx.x;   // 0 .. 262143 (u64 units)
    int kk  = idx & 1;
    int cg5 = (idx >> 1) & 31;
    int q   = (idx >> 6) & 7;
    int k2  = (idx >> 9) & 127;
    int dc  = (idx >> 16) & 3;
    int d = dc >> 1, c = dc & 1;
    int k  = 2 * k2 + kk;
    int gp = q >> 2;
    int jl = cg5 * 4 + (q & 3);
    int j  = c * 128 + jl;
    const float* U = d ? Ub : Uf;
    g_U7[idx] = pack2(U[(size_t)k * NG + gp * 512 + j],
                      U[(size_t)k * NG + gp * 512 + 256 + j]);
}

// ---------------------------------------------------------------------------
// Canonicalize mask to u8. mask[0][0], mask[0][1] guaranteed true (len >= 64):
// byte0==0 -> float32; byte1!=0 -> uint8; else -> int32.
// ---------------------------------------------------------------------------
__global__ void repack_mask_kernel(const unsigned char* __restrict__ raw)
{
    int idx = blockIdx.x * 256 + threadIdx.x;
    unsigned char b0 = raw[0], b1 = raw[1];
    unsigned char v;
    if (b0 == 0)      v = (((const float*)raw)[idx] != 0.0f);
    else if (b1 != 0) v = (raw[idx] != 0);
    else              v = (((const int*)raw)[idx] != 0);
    g_mask[idx] = v;
}

// ---------------------------------------------------------------------------
// Phase 1: xz = x @ W + b (R12: broadcast-A + cp.async double buffer).
// ---------------------------------------------------------------------------
#define BM 128
#define BN 128
#define BK 20
#define KT 300

__global__ __launch_bounds__(256, 2) void proj_kernel(
    const float* __restrict__ Wf, const float* __restrict__ bf,
    const float* __restrict__ Wb, const float* __restrict__ bb)
{
    __shared__ float As[2][BK][BM];
    __shared__ float Bs[2][BK][BN];

    const int tid = threadIdx.x;
    const int m0  = blockIdx.x * BM;
    const int d   = blockIdx.y >> 3;
    const int n0  = (blockIdx.y & 7) * BN;
    const float* __restrict__ W    = d ? Wb : Wf;
    const float* __restrict__ bias = d ? bb : bf;
    const int tc = tid & 15;
    const int tr = tid >> 4;

    const uint32_t a32 = smem_u32(As);
    const uint32_t b32 = smem_u32(Bs);

    u64 acc[8][4];
    {
        const float* bp = bias + n0 + tc * 8;
        u64 b0 = pack2(bp[0], bp[1]);
        u64 b1 = pack2(bp[2], bp[3]);
        u64 b2 = pack2(bp[4], bp[5]);
        u64 b3 = pack2(bp[6], bp[7]);
        #pragma unroll
        for (int i = 0; i < 8; i++){ acc[i][0]=b0; acc[i][1]=b1; acc[i][2]=b2; acc[i][3]=b3; }
    }

    auto load_tiles = [&](int it, int bf_){
        const int kt = it * BK;
        #pragma unroll
        for (int i = 0; i < 5; i++){
            int g = tid + i * 256;
            int ga = (g >= 640) ? g - 640 : g;
            int k  = ga >> 5;
            int cw = (ga & 31) * 4;
            if (g < 640)
                cp_async16(a32 + (uint32_t)(((bf_ * BK + k) * BM + cw) * 4),
                           g_xT + (size_t)(kt + k) * NM + m0 + cw);
            else
                cp_async16(b32 + (uint32_t)(((bf_ * BK + k) * BN + cw) * 4),
                           W + (size_t)(kt + k) * NG + n0 + cw);
        }
        cp_async_commit();
    };

    int buf = 0;
    load_tiles(0, 0);

    for (int it = 0; it < 15; ++it){
        if (it + 1 < 15){ load_tiles(it + 1, buf ^ 1); cp_async_wait1(); }
        else cp_async_wait0();
        __syncthreads();

        #pragma unroll
        for (int k = 0; k < BK; k++){
            float4 av0 = *(const float4*)&As[buf][k][tr * 8];
            float4 av1 = *(const float4*)&As[buf][k][tr * 8 + 4];
            u64 a[8] = { pack2(av0.x, av0.x), pack2(av0.y, av0.y),
                         pack2(av0.z, av0.z), pack2(av0.w, av0.w),
                         pack2(av1.x, av1.x), pack2(av1.y, av1.y),
                         pack2(av1.z, av1.z), pack2(av1.w, av1.w) };
            u64 b[4];
            {
                const ulonglong2* bp = (const ulonglong2*)&Bs[buf][k][tc * 8];
                ulonglong2 b01 = bp[0], b23 = bp[1];
                b[0]=b01.x; b[1]=b01.y; b[2]=b23.x; b[3]=b23.y;
            }
            #pragma unroll
            for (int i = 0; i < 8; i++){
                #pragma unroll
                for (int j = 0; j < 4; j++){
                    acc[i][j] = ffma2(a[i], b[j], acc[i][j]);
                }
            }
        }
        __syncthreads();
        buf ^= 1;
    }

    #pragma unroll
    for (int i = 0; i < 8; i++){
        size_t row = (size_t)d * NM + (size_t)(m0 + tr * 8 + i);
        ulonglong2* orow = (ulonglong2*)(g_xz + row * NG + n0 + tc * 8);
        ulonglong2 v0; v0.x = acc[i][0]; v0.y = acc[i][1];
        ulonglong2 v1; v1.x = acc[i][2]; v1.y = acc[i][3];
        orow[0] = v0; orow[1] = v1;
    }
}

// ---------------------------------------------------------------------------
// Phase 2: LSTM recurrence, 2-CTA clusters, 512 threads/CTA (4 warps/SMSP).
// Thread (cg5, kq, sh 0..3): 8 pair-cols over k-quarter kq for seq-quarter sh
//   ({3,2,3,2} seqs). Per k2: 8 LDG.128 U + 4 LDS.128 h + 16*SC FFMA2.
// Partials: slab kq*2 + (sh>>1), seq rows disjoint between quarter twins.
// Finalize over all 512 threads: 2 j x 1-2 seqs each.
// smem identical to R12 (152832 B).
// ---------------------------------------------------------------------------
#define LSTM_SMEM (2*256*12*8 + 8*5*8*32*8 + LNS*512*4 + LNS*NT)

template<int SC>
__device__ __forceinline__ void lstm_kloop(
    const u64* __restrict__ hb, const ulonglong2* __restrict__ Ubase,
    u64* __restrict__ pslab, int sl0, int cg5)
{
    u64 acc[8][SC];
    #pragma unroll
    for (int q = 0; q < 8; q++)
        #pragma unroll
        for (int s = 0; s < SC; s++) acc[q][s] = 0ull;

    #pragma unroll 4
    for (int i = 0; i < 32; i++){
        ulonglong2 Uq[8];
        #pragma unroll
        for (int q = 0; q < 8; q++) Uq[q] = Ubase[((size_t)i * 8 + q) * 32];
        // h rows for k = 2i and 2i+1; seq slots sl0 .. sl0+SC-1 (within 6-slot half).
        const u64* r0 = hb + (2 * i) * 12;
        const u64* r1 = hb + (2 * i + 1) * 12;
        u64 h0[SC], h1[SC];
        if (SC == 3){
            ulonglong2 p0 = ((const ulonglong2*)r0)[0], p1 = ((const ulonglong2*)r0)[1];
            ulonglong2 q0 = ((const ulonglong2*)r1)[0], q1 = ((const ulonglong2*)r1)[1];
            h0[0] = p0.x; h0[1] = p0.y; h0[2] = p1.x;
            h1[0] = q0.x; h1[1] = q0.y; h1[2] = q1.x;
        } else {
            ulonglong2 p1 = ((const ulonglong2*)r0)[1], p2 = ((const ulonglong2*)r0)[2];
            ulonglong2 q1 = ((const ulonglong2*)r1)[1], q2 = ((const ulonglong2*)r1)[2];
            h0[0] = p1.y; h0[1] = p2.x;
            h1[0] = q1.y; h1[1] = q2.x;
        }
        #pragma unroll
        for (int q = 0; q < 8; q++){
            #pragma unroll
            for (int s = 0; s < SC; s++){
                acc[q][s] = ffma2(h0[s], Uq[q].x, acc[q][s]);
                acc[q][s] = ffma2(h1[s], Uq[q].y, acc[q][s]);
            }
        }
    }

    #pragma unroll
    for (int s = 0; s < SC; s++)
        #pragma unroll
        for (int q = 0; q < 8; q++)
            pslab[(sl0 + s) * 256 + q * 32 + cg5] = acc[q][s];
}

__global__ __launch_bounds__(512, 1) __cluster_dims__(2, 1, 1)
void lstm_kernel(float* __restrict__ out)
{
    extern __shared__ __align__(16) char dsm[];
    u64*   sh_h    = (u64*)dsm;                              // [2][256][12]
    u64*   sh_part = (u64*)(dsm + 2*256*12*8);               // [8][5][8][32]
    float* sh_xz   = (float*)(dsm + 2*256*12*8 + 8*5*8*32*8);// [10][512]
    unsigned char* sh_m = (unsigned char*)(dsm + 2*256*12*8 + 8*5*8*32*8 + LNS*512*4);

    const int tid  = threadIdx.x;
    const int cg5  = tid & 31;
    const int kq   = (tid >> 5) & 3;
    const int sh   = tid >> 7;            // seq quarter 0..3
    const int half = sh >> 1;
    const int qp   = sh & 1;              // 0: 3 seqs (slots 0-2), 1: 2 seqs (slots 3-4)
    const int c    = blockIdx.x;          // == cluster rank
    const int grp  = blockIdx.y;
    const int d    = blockIdx.z;
    const int dc   = d * 2 + c;
    const int seq0 = grp * LNS;

    uint32_t rank; asm("mov.u32 %0, %%cluster_ctarank;" : "=r"(rank));
    const uint32_t my_h   = smem_u32(sh_h);
    const uint32_t peer_h = mapa_u32(my_h, rank ^ 1);
    const uint32_t xz_s32 = smem_u32(sh_xz);

    for (int i = tid; i < 2 * 256 * 12; i += 512) sh_h[i] = 0ull;
    for (int i = tid; i < LNS * NT; i += 512)
        sh_m[i] = g_mask[(size_t)seq0 * NT + i];
    __syncthreads();

    const float* xzb = g_xz + (size_t)d * NM * NG + (size_t)seq0 * NT * NG;

    // Finalize role: 512 threads -> 64 j-pairs x 8 seq groups {2,1,1,1,2,1,1,1}.
    const int jl2   = tid & 63;
    const int sq    = tid >> 6;
    const int fs0   = sq + (sq >= 1 ? 1 : 0) + (sq >= 5 ? 1 : 0);
    const int fscnt = (sq == 0 || sq == 4) ? 2 : 1;
    float h_st[2][2], c_st[2][2];
    #pragma unroll
    for (int a = 0; a < 2; a++)
        #pragma unroll
        for (int b = 0; b < 2; b++){ h_st[a][b] = 0.f; c_st[a][b] = 0.f; }

    const ulonglong2* Ubase = (const ulonglong2*)g_U7
                            + ((size_t)(dc * 128 + kq * 32) * 8) * 32 + cg5;
    u64* pslab = sh_part + ((size_t)(kq * 2 + half) * 5) * 256;

    int rb = 0;
    for (int step = 0; step < NT; ++step){
        const int t = d ? (NT - 1 - step) : step;

        #pragma unroll
        for (int i = tid; i < 1280; i += 512){
            int s = i >> 7;
            int o = i & 127;
            int gcol = ((o >> 5) << 8) + c * 128 + ((o & 31) << 2);
            const float* src = xzb + ((size_t)s * NT + t) * NG + gcol;
            cp_async16(xz_s32 + (uint32_t)((s * 512 + (o >> 5) * 128 + ((o & 31) << 2) ) * 4), src);
        }
        cp_async_commit();

        const u64* hb = sh_h + (size_t)rb * 256 * 12 + (size_t)(kq * 64) * 12 + half * 6;
        if (qp == 0) lstm_kloop<3>(hb, Ubase, pslab, 0, cg5);
        else         lstm_kloop<2>(hb, Ubase, pslab, 3, cg5);

        cp_async_wait0();
        __syncthreads();

        {
            const int wb = rb ^ 1;
            #pragma unroll
            for (int w = 0; w < 2; w++){
                const int jl  = 2 * jl2 + w;
                const int j   = c * 128 + jl;
                const int qm  = jl & 3;
                const int cgx = jl >> 2;
                float* outc = out + ((size_t)(seq0) * NT + t) * (2 * NH) + d * NH + j;
                #pragma unroll
                for (int si = 0; si < 2; si++){
                    if (si < fscnt){
                        const int s   = fs0 + si;
                        const int shs = (s >= 5);
                        const int sl  = s - 5 * shs;
                        const u64* pif = sh_part + ((size_t)sl * 256 + qm * 32 + cgx) + (size_t)shs * 5 * 256;
                        const u64* pgo = pif + 128;
                        u64 zif = addf32x2(addf32x2(pif[0], pif[2560]),
                                           addf32x2(pif[5120], pif[7680]));
                        u64 zgo = addf32x2(addf32x2(pgo[0], pgo[2560]),
                                           addf32x2(pgo[5120], pgo[7680]));
                        const float* xs = sh_xz + s * 512;
                        zif = addf32x2(zif, pack2(xs[jl], xs[128 + jl]));
                        zgo = addf32x2(zgo, pack2(xs[256 + jl], xs[384 + jl]));
                        float zi, zf, zg, zo;
                        unpack2(zif, zi, zf);
                        unpack2(zgo, zg, zo);
                        float ig = __fdividef(1.f, 1.f + __expf(-zi));
                        float fg = __fdividef(1.f, 1.f + __expf(-zf));
                        float gg = 1.f - __fdividef(2.f, __expf(2.f * zg) + 1.f);
                        float og = __fdividef(1.f, 1.f + __expf(-zo));
                        float cn = fg * c_st[w][si] + ig * gg;
                        float hn = og * (1.f - __fdividef(2.f, __expf(2.f * cn) + 1.f));
                        if (sh_m[s * NT + t]){ c_st[w][si] = cn; h_st[w][si] = hn; }
                        u64 hd = pack2(h_st[w][si], h_st[w][si]);
                        size_t hidx = ((size_t)wb * 256 + j) * 12 + shs * 6 + sl;
                        sh_h[hidx] = hd;
                        st_cluster_u64(peer_h + (uint32_t)(hidx * 8), hd);
                        outc[(size_t)s * NT * (2 * NH)] = h_st[w][si];
                    }
                }
            }
        }
        cluster_sync();
        rb ^= 1;
    }
}

extern "C" void kernel_launch(void* const* d_in, const int* in_sizes, int n_in,
                              void* d_out, int out_size)
{
    const float*         facts = (const float*)d_in[0];
    const unsigned char* mask  = (const unsigned char*)d_in[1];
    const float*         Wf    = (const float*)d_in[2];
    const float*         Uf    = (const float*)d_in[3];
    const float*         bf    = (const float*)d_in[4];
    const float*         Wb    = (const float*)d_in[5];
    const float*         Ub    = (const float*)d_in[6];
    const float*         bb    = (const float*)d_in[7];
    float* out = (float*)d_out;

    cudaFuncSetAttribute(lstm_kernel, cudaFuncAttributeMaxDynamicSharedMemorySize, LSTM_SMEM);

    repack_x_kernel<<<(int)(((size_t)ND * NM) / 256), 256>>>(facts);
    repack_u_kernel<<<1024, 256>>>(Uf, Ub);
    repack_mask_kernel<<<SEQS * NT / 256, 256>>>(mask);
    proj_kernel<<<dim3(NM / BM, 16), 256>>>(Wf, bf, Wb, bb);
    lstm_kernel<<<dim3(2, SEQS / LNS, 2), 512, LSTM_SMEM>>>(out);
}

// round 16
// speedup vs baseline: 1.1667x; 1.1667x over previous
#include <cuda_runtime.h>
#include <cstdint>

typedef unsigned long long u64;

#define NB 16
#define NF 20
#define NT 128
#define ND 300
#define NH 256
#define NG 1024   // 4*H
#define SEQS 320  // NB*NF
#define NM 40960  // SEQS*NT
#define LNS 10    // sequences per lstm cluster (32 groups)

// Scratch: xz 335 MB, xT 49 MB, U repack 2 MB, mask 40 KB.
__device__ float g_xz[2ull * NM * NG];
__device__ float g_xT[(size_t)ND * NM];        // [k][m] transposed input
// U layout (R7): u64 idx = (((dc*128 + k2)*8 + q)*32 + cg5)*2 + kk
__device__ u64 g_U7[4 * 128 * 8 * 32 * 2];
__device__ unsigned char g_mask[SEQS * NT];

__device__ __forceinline__ u64 pack2(float a, float b){
    u64 r; asm("mov.b64 %0, {%1, %2};" : "=l"(r) : "f"(a), "f"(b)); return r;
}
__device__ __forceinline__ void unpack2(u64 v, float& a, float& b){
    asm("mov.b64 {%0, %1}, %2;" : "=f"(a), "=f"(b) : "l"(v));
}
__device__ __forceinline__ u64 ffma2(u64 a, u64 b, u64 c){
    u64 d; asm("fma.rn.f32x2 %0, %1, %2, %3;" : "=l"(d) : "l"(a), "l"(b), "l"(c)); return d;
}
__device__ __forceinline__ u64 addf32x2(u64 a, u64 b){
    u64 d; asm("add.rn.f32x2 %0, %1, %2;" : "=l"(d) : "l"(a), "l"(b)); return d;
}
__device__ __forceinline__ uint32_t smem_u32(const void* p){
    uint32_t a; asm("{ .reg .u64 t; cvta.to.shared.u64 t, %1; cvt.u32.u64 %0, t; }" : "=r"(a) : "l"(p));
    return a;
}
__device__ __forceinline__ uint32_t mapa_u32(uint32_t addr, uint32_t rank){
    uint32_t r; asm("mapa.shared::cluster.u32 %0, %1, %2;" : "=r"(r) : "r"(addr), "r"(rank));
    return r;
}
__device__ __forceinline__ void st_cluster_u64(uint32_t addr, u64 v){
    asm volatile("st.shared::cluster.u64 [%0], %1;" :: "r"(addr), "l"(v) : "memory");
}
__device__ __forceinline__ void cluster_sync(){
    asm volatile("barrier.cluster.arrive.aligned;\n\tbarrier.cluster.wait.aligned;" ::: "memory");
}
__device__ __forceinline__ void cp_async16(uint32_t sdst, const void* gsrc){
    asm volatile("cp.async.ca.shared.global [%0], [%1], 16;" :: "r"(sdst), "l"(gsrc) : "memory");
}
__device__ __forceinline__ void cp_async_commit(){
    asm volatile("cp.async.commit_group;" ::: "memory");
}
__device__ __forceinline__ void cp_async_wait0(){
    asm volatile("cp.async.wait_group 0;" ::: "memory");
}

// ---------------------------------------------------------------------------
// Transpose x -> g_xT[k][m].
// ---------------------------------------------------------------------------
__global__ void repack_x_kernel(const float* __restrict__ x)
{
    size_t idx = (size_t)blockIdx.x * 256 + threadIdx.x;
    int k = (int)(idx / NM);
    int m = (int)(idx % NM);
    g_xT[idx] = x[(size_t)m * ND + k];
}

// ---------------------------------------------------------------------------
// Repack U into the R7 chunked layout.
// ---------------------------------------------------------------------------
__global__ void repack_u_kernel(const float* __restrict__ Uf, const float* __restrict__ Ub)
{
    int idx = blockIdx.x * 256 + threadIdx.x;   // 0 .. 262143 (u64 units)
    int kk  = idx & 1;
    int cg5 = (idx >> 1) & 31;
    int q   = (idx >> 6) & 7;
    int k2  = (idx >> 9) & 127;
    int dc  = (idx >> 16) & 3;
    int d = dc >> 1, c = dc & 1;
    int k  = 2 * k2 + kk;
    int gp = q >> 2;
    int jl = cg5 * 4 + (q & 3);
    int j  = c * 128 + jl;
    const float* U = d ? Ub : Uf;
    g_U7[idx] = pack2(U[(size_t)k * NG + gp * 512 + j],
                      U[(size_t)k * NG + gp * 512 + 256 + j]);
}

// ---------------------------------------------------------------------------
// Canonicalize mask to u8. mask[0][0], mask[0][1] guaranteed true (len >= 64):
// byte0==0 -> float32; byte1!=0 -> uint8; else -> int32.
// ---------------------------------------------------------------------------
__global__ void repack_mask_kernel(const unsigned char* __restrict__ raw)
{
    int idx = blockIdx.x * 256 + threadIdx.x;
    unsigned char b0 = raw[0], b1 = raw[1];
    unsigned char v;
    if (b0 == 0)      v = (((const float*)raw)[idx] != 0.0f);
    else if (b1 != 0) v = (raw[idx] != 0);
    else              v = (((const int*)raw)[idx] != 0);
    g_mask[idx] = v;
}

// ---------------------------------------------------------------------------
// Phase 1: xz = x @ W + b.  Broadcast-A + cp.async double buffer,
// SINGLE __syncthreads per k-tile: wait -> sync -> load(it+1) -> compute(it).
// ---------------------------------------------------------------------------
#define BM 128
#define BN 128
#define BK 20
#define KT 300

__global__ __launch_bounds__(256, 2) void proj_kernel(
    const float* __restrict__ Wf, const float* __restrict__ bf,
    const float* __restrict__ Wb, const float* __restrict__ bb)
{
    __shared__ float As[2][BK][BM];
    __shared__ float Bs[2][BK][BN];

    const int tid = threadIdx.x;
    const int m0  = blockIdx.x * BM;
    const int d   = blockIdx.y >> 3;
    const int n0  = (blockIdx.y & 7) * BN;
    const float* __restrict__ W    = d ? Wb : Wf;
    const float* __restrict__ bias = d ? bb : bf;
    const int tc = tid & 15;
    const int tr = tid >> 4;

    const uint32_t a32 = smem_u32(As);
    const uint32_t b32 = smem_u32(Bs);

    u64 acc[8][4];
    {
        const float* bp = bias + n0 + tc * 8;
        u64 b0 = pack2(bp[0], bp[1]);
        u64 b1 = pack2(bp[2], bp[3]);
        u64 b2 = pack2(bp[4], bp[5]);
        u64 b3 = pack2(bp[6], bp[7]);
        #pragma unroll
        for (int i = 0; i < 8; i++){ acc[i][0]=b0; acc[i][1]=b1; acc[i][2]=b2; acc[i][3]=b3; }
    }

    auto load_tiles = [&](int it, int bf_){
        const int kt = it * BK;
        #pragma unroll
        for (int i = 0; i < 5; i++){
            int g = tid + i * 256;
            int ga = (g >= 640) ? g - 640 : g;
            int k  = ga >> 5;
            int cw = (ga & 31) * 4;
            if (g < 640)
                cp_async16(a32 + (uint32_t)(((bf_ * BK + k) * BM + cw) * 4),
                           g_xT + (size_t)(kt + k) * NM + m0 + cw);
            else
                cp_async16(b32 + (uint32_t)(((bf_ * BK + k) * BN + cw) * 4),
                           W + (size_t)(kt + k) * NG + n0 + cw);
        }
        cp_async_commit();
    };

    int buf = 0;
    load_tiles(0, 0);

    for (int it = 0; it < 15; ++it){
        // All groups <= it complete (group it had one full iteration in flight).
        cp_async_wait0();
        __syncthreads();   // data visible; also: everyone finished reading buf^1 (iter it-1)
        if (it + 1 < 15) load_tiles(it + 1, buf ^ 1);

        #pragma unroll
        for (int k = 0; k < BK; k++){
            float4 av0 = *(const float4*)&As[buf][k][tr * 8];
            float4 av1 = *(const float4*)&As[buf][k][tr * 8 + 4];
            u64 a[8] = { pack2(av0.x, av0.x), pack2(av0.y, av0.y),
                         pack2(av0.z, av0.z), pack2(av0.w, av0.w),
                         pack2(av1.x, av1.x), pack2(av1.y, av1.y),
                         pack2(av1.z, av1.z), pack2(av1.w, av1.w) };
            u64 b[4];
            {
                const ulonglong2* bp = (const ulonglong2*)&Bs[buf][k][tc * 8];
                ulonglong2 b01 = bp[0], b23 = bp[1];
                b[0]=b01.x; b[1]=b01.y; b[2]=b23.x; b[3]=b23.y;
            }
            #pragma unroll
            for (int i = 0; i < 8; i++){
                #pragma unroll
                for (int j = 0; j < 4; j++){
                    acc[i][j] = ffma2(a[i], b[j], acc[i][j]);
                }
            }
        }
        buf ^= 1;
    }

    #pragma unroll
    for (int i = 0; i < 8; i++){
        size_t row = (size_t)d * NM + (size_t)(m0 + tr * 8 + i);
        ulonglong2* orow = (ulonglong2*)(g_xz + row * NG + n0 + tc * 8);
        ulonglong2 v0; v0.x = acc[i][0]; v0.y = acc[i][1];
        ulonglong2 v1; v1.x = acc[i][2]; v1.y = acc[i][3];
        orow[0] = v0; orow[1] = v1;
    }
}

// ---------------------------------------------------------------------------
// Phase 2: LSTM recurrence — exact R14 kernel (proven 2580-us build):
// 256 threads, 2-CTA clusters, fast divides in finalize.
// ---------------------------------------------------------------------------
#define LSTM_SMEM (2*256*12*8 + 8*5*8*32*8 + LNS*512*4 + LNS*NT)

__global__ __launch_bounds__(256, 1) __cluster_dims__(2, 1, 1)
void lstm_kernel(float* __restrict__ out)
{
    extern __shared__ __align__(16) char dsm[];
    u64*   sh_h    = (u64*)dsm;                              // [2][256][12]
    u64*   sh_part = (u64*)(dsm + 2*256*12*8);               // [8][5][8][32]
    float* sh_xz   = (float*)(dsm + 2*256*12*8 + 8*5*8*32*8);// [10][512]
    unsigned char* sh_m = (unsigned char*)(dsm + 2*256*12*8 + 8*5*8*32*8 + LNS*512*4);

    const int tid  = threadIdx.x;
    const int cg5  = tid & 31;
    const int kq   = (tid >> 5) & 3;
    const int sh   = tid >> 7;
    const int c    = blockIdx.x;          // == cluster rank
    const int grp  = blockIdx.y;
    const int d    = blockIdx.z;
    const int dc   = d * 2 + c;
    const int seq0 = grp * LNS;

    uint32_t rank; asm("mov.u32 %0, %%cluster_ctarank;" : "=r"(rank));
    const uint32_t my_h   = smem_u32(sh_h);
    const uint32_t peer_h = mapa_u32(my_h, rank ^ 1);
    const uint32_t xz_s32 = smem_u32(sh_xz);

    for (int i = tid; i < 2 * 256 * 12; i += 256) sh_h[i] = 0ull;
    for (int i = tid; i < LNS * NT; i += 256)
        sh_m[i] = g_mask[(size_t)seq0 * NT + i];
    __syncthreads();

    const float* xzb = g_xz + (size_t)d * NM * NG + (size_t)seq0 * NT * NG;

    const int jl2   = tid & 63;
    const int sq    = tid >> 6;
    const int fs0   = (sq == 0) ? 0 : (sq == 1) ? 3 : (sq == 2) ? 5 : 8;
    const int fscnt = (sq & 1) ? 2 : 3;
    float h_st[2][3], c_st[2][3];
    #pragma unroll
    for (int a = 0; a < 2; a++)
        #pragma unroll
        for (int b = 0; b < 3; b++){ h_st[a][b] = 0.f; c_st[a][b] = 0.f; }

    const ulonglong2* Ubase = (const ulonglong2*)g_U7
                            + ((size_t)(dc * 128 + kq * 32) * 8) * 32 + cg5;
    u64* pbase = sh_part + ((size_t)(kq * 2 + sh) * 5) * 256;

    int rb = 0;
    for (int step = 0; step < NT; ++step){
        const int t = d ? (NT - 1 - step) : step;

        #pragma unroll
        for (int i = tid; i < 1280; i += 256){
            int s = i >> 7;
            int o = i & 127;
            int gcol = ((o >> 5) << 8) + c * 128 + ((o & 31) << 2);
            const float* src = xzb + ((size_t)s * NT + t) * NG + gcol;
            cp_async16(xz_s32 + (uint32_t)((s * 512 + (o >> 5) * 128 + ((o & 31) << 2)) * 4), src);
        }
        cp_async_commit();

        u64 acc[8][5];
        #pragma unroll
        for (int q = 0; q < 8; q++)
            #pragma unroll
            for (int s = 0; s < 5; s++) acc[q][s] = 0ull;

        const u64* hb = sh_h + (size_t)rb * 256 * 12 + (size_t)(kq * 64) * 12 + sh * 6;
        #pragma unroll 4
        for (int i = 0; i < 32; i++){
            ulonglong2 Uq[8];
            #pragma unroll
            for (int q = 0; q < 8; q++) Uq[q] = Ubase[((size_t)i * 8 + q) * 32];
            const ulonglong2* h0p = (const ulonglong2*)(hb + (2 * i) * 12);
            const ulonglong2* h1p = (const ulonglong2*)(hb + (2 * i + 1) * 12);
            ulonglong2 a0 = h0p[0], a1 = h0p[1], a2 = h0p[2];
            ulonglong2 b0 = h1p[0], b1 = h1p[1], b2 = h1p[2];
            u64 h0[5] = { a0.x, a0.y, a1.x, a1.y, a2.x };
            u64 h1[5] = { b0.x, b0.y, b1.x, b1.y, b2.x };
            #pragma unroll
            for (int q = 0; q < 8; q++){
                #pragma unroll
                for (int s = 0; s < 5; s++){
                    acc[q][s] = ffma2(h0[s], Uq[q].x, acc[q][s]);
                    acc[q][s] = ffma2(h1[s], Uq[q].y, acc[q][s]);
                }
            }
        }

        #pragma unroll
        for (int s = 0; s < 5; s++)
            #pragma unroll
            for (int q = 0; q < 8; q++)
                pbase[s * 256 + q * 32 + cg5] = acc[q][s];

        cp_async_wait0();
        __syncthreads();

        {
            const int wb = rb ^ 1;
            #pragma unroll
            for (int w = 0; w < 2; w++){
                const int jl  = 2 * jl2 + w;
                const int j   = c * 128 + jl;
                const int qm  = jl & 3;
                const int cgx = jl >> 2;
                float* outc = out + ((size_t)(seq0) * NT + t) * (2 * NH) + d * NH + j;
                #pragma unroll
                for (int si = 0; si < 3; si++){
                    if (si < fscnt){
                        const int s   = fs0 + si;
                        const int shs = (s >= 5);
                        const int sl  = s - 5 * shs;
                        const u64* pif = sh_part + ((size_t)sl * 256 + qm * 32 + cgx) + (size_t)shs * 5 * 256;
                        const u64* pgo = pif + 128;
                        u64 zif = addf32x2(addf32x2(pif[0], pif[2560]),
                                           addf32x2(pif[5120], pif[7680]));
                        u64 zgo = addf32x2(addf32x2(pgo[0], pgo[2560]),
                                           addf32x2(pgo[5120], pgo[7680]));
                        const float* xs = sh_xz + s * 512;
                        zif = addf32x2(zif, pack2(xs[jl], xs[128 + jl]));
                        zgo = addf32x2(zgo, pack2(xs[256 + jl], xs[384 + jl]));
                        float zi, zf, zg, zo;
                        unpack2(zif, zi, zf);
                        unpack2(zgo, zg, zo);
                        float ig = __fdividef(1.f, 1.f + __expf(-zi));
                        float fg = __fdividef(1.f, 1.f + __expf(-zf));
                        float gg = 1.f - __fdividef(2.f, __expf(2.f * zg) + 1.f);
                        float og = __fdividef(1.f, 1.f + __expf(-zo));
                        float cn = fg * c_st[w][si] + ig * gg;
                        float hn = og * (1.f - __fdividef(2.f, __expf(2.f * cn) + 1.f));
                        if (sh_m[s * NT + t]){ c_st[w][si] = cn; h_st[w][si] = hn; }
                        u64 hd = pack2(h_st[w][si], h_st[w][si]);
                        size_t hidx = ((size_t)wb * 256 + j) * 12 + shs * 6 + sl;
                        sh_h[hidx] = hd;
                        st_cluster_u64(peer_h + (uint32_t)(hidx * 8), hd);
                        outc[(size_t)s * NT * (2 * NH)] = h_st[w][si];
                    }
                }
            }
        }
        cluster_sync();
        rb ^= 1;
    }
}

extern "C" void kernel_launch(void* const* d_in, const int* in_sizes, int n_in,
                              void* d_out, int out_size)
{
    const float*         facts = (const float*)d_in[0];
    const unsigned char* mask  = (const unsigned char*)d_in[1];
    const float*         Wf    = (const float*)d_in[2];
    const float*         Uf    = (const float*)d_in[3];
    const float*         bf    = (const float*)d_in[4];
    const float*         Wb    = (const float*)d_in[5];
    const float*         Ub    = (const float*)d_in[6];
    const float*         bb    = (const float*)d_in[7];
    float* out = (float*)d_out;

    cudaFuncSetAttribute(lstm_kernel, cudaFuncAttributeMaxDynamicSharedMemorySize, LSTM_SMEM);

    repack_x_kernel<<<(int)(((size_t)ND * NM) / 256), 256>>>(facts);
    repack_u_kernel<<<1024, 256>>>(Uf, Ub);
    repack_mask_kernel<<<SEQS * NT / 256, 256>>>(mask);
    proj_kernel<<<dim3(NM / BM, 16), 256>>>(Wf, bf, Wb, bb);
    lstm_kernel<<<dim3(2, SEQS / LNS, 2), 256, LSTM_SMEM>>>(out);
}